// round 13
// baseline (speedup 1.0000x reference)
#include <cuda_runtime.h>
#include <cstdint>

#define BATCH 32
#define NH    16
#define DK    64
#define DM    1024
#define TC    4096

#define NKV_CTA 32
#define NATTN   (BATCH * NH)

// Scratch (device globals — no allocation allowed)
__device__ float g_qp[BATCH * DM];   // scaled query projection
__device__ float g_kp[BATCH * DM];   // new-token key projection
__device__ float g_vp[BATCH * DM];   // new-token value projection
__device__ float g_x [BATCH * DM];   // attention output (pre out-proj)
__device__ int   g_kv_done;          // zero-init; reset by out-proj launch

// Packed dual-FMA (sm_103a FFMA2; PTX-only)
__device__ __forceinline__ void ffma2(unsigned long long& d,
                                      unsigned long long a,
                                      unsigned long long b)
{
    asm("fma.rn.f32x2 %0, %1, %2, %0;" : "+l"(d) : "l"(a), "l"(b));
}
__device__ __forceinline__ float pair_sum(unsigned long long v)
{
    return __uint_as_float((unsigned)v) + __uint_as_float((unsigned)(v >> 32));
}

// ---------------------------------------------------------------------------
// GEMV projection (R11-proven shape): grid (DM/8, 1, 4), block 128.
// CTA owns 8 rows x 8 batches as two cp.async-staged groups of 4; FFMA2.
// mode 0: q-projection only (W0=wq -> g_qp, scale 1/sqrt(DK))
// mode 1: out-projection (act = g_x device symbol, W0 -> out_ext) + resets
//         g_kv_done for the next graph replay.
// ---------------------------------------------------------------------------
__global__ void __launch_bounds__(128)
proj_kernel(int mode,
            const float* __restrict__ act_ext,
            const float* __restrict__ W0, const float* __restrict__ B0,
            float* __restrict__ out_ext,
            float qscale)
{
    if (mode == 1 && blockIdx.x == 0 && blockIdx.z == 0 && threadIdx.x == 0)
        g_kv_done = 0;

    const float* act  = (mode == 1) ? g_x : act_ext;
    const float* W    = W0;
    const float* bias = B0;
    float* out        = (mode == 1) ? out_ext : g_qp;
    const float scale = (mode == 1) ? 1.0f : qscale;

    const int warp = threadIdx.x >> 5;
    const int lane = threadIdx.x & 31;
    const int j0   = (blockIdx.x * 4 + warp) * 2;   // 2 rows per warp
    const int b0   = blockIdx.z * 8;                // 8 batches per z-slice

    __shared__ __align__(16) float s_act[2][4 * DM];   // 2 x 16 KB act groups

    {
        const float* src0 = act + (size_t)b0 * DM;
        const float* src1 = act + (size_t)(b0 + 4) * DM;
        uint32_t sb0 = (uint32_t)__cvta_generic_to_shared(s_act[0]);
        uint32_t sb1 = (uint32_t)__cvta_generic_to_shared(s_act[1]);
#pragma unroll
        for (int i = 0; i < 8; i++) {
            int u = i * 128 + threadIdx.x;
            asm volatile("cp.async.cg.shared.global [%0], [%1], 16;"
                         :: "r"(sb0 + u * 16), "l"(src0 + u * 4) : "memory");
        }
        asm volatile("cp.async.commit_group;" ::: "memory");
#pragma unroll
        for (int i = 0; i < 8; i++) {
            int u = i * 128 + threadIdx.x;
            asm volatile("cp.async.cg.shared.global [%0], [%1], 16;"
                         :: "r"(sb1 + u * 16), "l"(src1 + u * 4) : "memory");
        }
        asm volatile("cp.async.commit_group;" ::: "memory");
    }

    ulonglong2 w[2][8];
#pragma unroll
    for (int r = 0; r < 2; r++) {
        const float* Wr = W + (size_t)(j0 + r) * DM;
#pragma unroll
        for (int c = 0; c < 8; c++)
            w[r][c] = *(const ulonglong2*)(Wr + c * 128 + lane * 4);
    }
    const float bias0 = bias[j0], bias1 = bias[j0 + 1];

    asm volatile("cp.async.wait_group 1;" ::: "memory");
    __syncthreads();

#pragma unroll
    for (int g = 0; g < 2; g++) {
        const float* sa = s_act[g];
        unsigned long long a2[4][2];
#pragma unroll
        for (int b = 0; b < 4; b++) { a2[b][0] = 0ull; a2[b][1] = 0ull; }

#pragma unroll
        for (int c = 0; c < 8; c++) {
#pragma unroll
            for (int b = 0; b < 4; b++) {
                ulonglong2 x = *(const ulonglong2*)&sa[b * DM + c * 128 + lane * 4];
                ffma2(a2[b][0], x.x, w[0][c].x);
                ffma2(a2[b][0], x.y, w[0][c].y);
                ffma2(a2[b][1], x.x, w[1][c].x);
                ffma2(a2[b][1], x.y, w[1][c].y);
            }
        }

        float a[4][2];
#pragma unroll
        for (int b = 0; b < 4; b++) {
            a[b][0] = pair_sum(a2[b][0]);
            a[b][1] = pair_sum(a2[b][1]);
        }
#pragma unroll
        for (int off = 16; off; off >>= 1) {
#pragma unroll
            for (int b = 0; b < 4; b++) {
                a[b][0] += __shfl_xor_sync(0xffffffffu, a[b][0], off);
                a[b][1] += __shfl_xor_sync(0xffffffffu, a[b][1], off);
            }
        }

        if (lane == 0) {
            const int bb0 = b0 + g * 4;
#pragma unroll
            for (int b = 0; b < 4; b++) {
                out[(size_t)(bb0 + b) * DM + j0]     = (a[b][0] + bias0) * scale;
                out[(size_t)(bb0 + b) * DM + j0 + 1] = (a[b][1] + bias1) * scale;
            }
        }

        if (g == 0) {
            asm volatile("cp.async.wait_group 0;" ::: "memory");
            __syncthreads();
        }
    }
}

// ---------------------------------------------------------------------------
// Fused kernel, grid = 32 + 512 CTAs x 256 threads, __launch_bounds__(256,4)
// so ALL 544 CTAs are wave-1 resident (the R6 regression was the missing
// register cap -> 3 CTAs/SM -> 2 waves).
//   bid 0..31   : register-lean k/v-projection producers (~20us, hidden
//                 under the consumers' ~150us HBM stream)
//   bid 32..543 : attention consumers (R7-proven body, HBM roofline)
// Consumers poll g_kv_done (volatile) only AFTER streaming the cache.
// ---------------------------------------------------------------------------
__global__ void __launch_bounds__(256, 4)
fused_attn(const float* __restrict__ act,
           const float* __restrict__ Kc, const float* __restrict__ Vc,
           const float* __restrict__ wk, const float* __restrict__ bk,
           const float* __restrict__ wv, const float* __restrict__ bv)
{
    const int cta  = blockIdx.x;
    const int tid  = threadIdx.x;
    const int warp = tid >> 5;
    const int lane = tid & 31;

    if (cta < NKV_CTA) {
        // ===== k/v producer: 8 rows/warp, register-lean (acc[8]+w4+x4) =====
        const int gw = cta * 8 + warp;            // 0..255
        for (int r = 0; r < 8; r++) {
            int ridx = gw * 8 + r;                // 0..2047
            const float* W; const float* bias; float* out;
            if (ridx < 1024) { W = wk; bias = bk; out = g_kp; }
            else { ridx -= 1024; W = wv; bias = bv; out = g_vp; }
            const float* Wr = W + (size_t)ridx * DM;
            const float bval = bias[ridx];

            for (int p = 0; p < 4; p++) {         // 4 passes x 8 batches
                float acc[8];
#pragma unroll
                for (int i = 0; i < 8; i++) acc[i] = 0.0f;
                for (int c = 0; c < 8; c++) {     // weights re-read (L1-hit)
                    float4 w4 = *(const float4*)(Wr + c * 128 + lane * 4);
#pragma unroll
                    for (int bb = 0; bb < 8; bb++) {
                        float4 x = *(const float4*)(act + (size_t)(p * 8 + bb) * DM
                                                    + c * 128 + lane * 4);
                        acc[bb] += x.x * w4.x + x.y * w4.y + x.z * w4.z + x.w * w4.w;
                    }
                }
#pragma unroll
                for (int off = 16; off; off >>= 1)
#pragma unroll
                    for (int bb = 0; bb < 8; bb++)
                        acc[bb] += __shfl_xor_sync(0xffffffffu, acc[bb], off);
                if (lane == 0)
#pragma unroll
                    for (int bb = 0; bb < 8; bb++)
                        out[(size_t)(p * 8 + bb) * DM + ridx] = acc[bb] + bval;
            }
        }
        __syncthreads();
        if (tid == 0) {
            __threadfence();
            atomicAdd(&g_kv_done, 1);
        }
        return;
    }

    // ===== attention consumer (R7-proven, HBM roofline — unchanged) =====
    const int bh   = cta - NKV_CTA;   // 0..511
    const int b    = bh >> 4;
    const int h    = bh & 15;
    const int half = lane >> 4;
    const int li   = lane & 15;

    __shared__ __align__(16) float sqf[DK];
    __shared__ float  sm[16], sl[16];
    __shared__ float4 so[16][16];
    __shared__ float  red2[2];

    if (tid < DK) sqf[tid] = g_qp[b * DM + h * DK + tid];   // pre-scaled
    __syncthreads();

    const float4 q4 = *(const float4*)&sqf[4 * li];

    const float* Kp = Kc + (size_t)bh * TC * DK + (size_t)half * DK + 4 * li;
    const float* Vp = Vc + (size_t)bh * TC * DK + (size_t)half * DK + 4 * li;

    float  m = -1e30f;
    float  l = 0.0f;
    float4 o = make_float4(0.f, 0.f, 0.f, 0.f);

    const int t0 = warp * (TC / 8);   // 512 keys/warp; 4-key blocks per half
    for (int t = t0; t < t0 + TC / 8; t += 8) {
        float4 kk[4], vv[4];
#pragma unroll
        for (int i = 0; i < 4; i++)
            kk[i] = __ldcs((const float4*)(Kp + (size_t)(t + 2 * i) * DK));
#pragma unroll
        for (int i = 0; i < 4; i++)
            vv[i] = __ldcs((const float4*)(Vp + (size_t)(t + 2 * i) * DK));

        float s[4];
#pragma unroll
        for (int i = 0; i < 4; i++)
            s[i] = kk[i].x * q4.x + kk[i].y * q4.y + kk[i].z * q4.z + kk[i].w * q4.w;
#pragma unroll
        for (int off = 8; off; off >>= 1)
#pragma unroll
            for (int i = 0; i < 4; i++)
                s[i] += __shfl_xor_sync(0xffffffffu, s[i], off);

        float bm = fmaxf(fmaxf(s[0], s[1]), fmaxf(s[2], s[3]));
        float mn = fmaxf(m, bm);

        float p[4];
#pragma unroll
        for (int i = 0; i < 4; i++) p[i] = __expf(s[i] - mn);

        float  lp = 0.0f;
        float4 op = make_float4(0.f, 0.f, 0.f, 0.f);
#pragma unroll
        for (int i = 0; i < 4; i++) {
            lp   += p[i];
            op.x += p[i] * vv[i].x;
            op.y += p[i] * vv[i].y;
            op.z += p[i] * vv[i].z;
            op.w += p[i] * vv[i].w;
        }

        float sc = __expf(m - mn);
        l   = l   * sc + lp;
        o.x = o.x * sc + op.x;
        o.y = o.y * sc + op.y;
        o.z = o.z * sc + op.z;
        o.w = o.w * sc + op.w;
        m   = mn;
    }

    // Publish partial states; wait for kv producers (long done by now).
    const int idx = warp * 2 + half;
    if (li == 0) { sm[idx] = m; sl[idx] = l; }
    so[idx][li] = o;
    if (tid == 0) {
        while (*(volatile int*)&g_kv_done < NKV_CTA) __nanosleep(100);
        __threadfence();
    }
    __syncthreads();

    // Merge 16 states + appended token. Threads 0..63 own one dim each.
    float prod = 0.0f, M = -1e30f, L = 0.0f, O = 0.0f, vn = 0.0f;
    if (tid < DK) {
        const int d = tid;
        M = sm[0];
#pragma unroll
        for (int i = 1; i < 16; i++) M = fmaxf(M, sm[i]);
#pragma unroll
        for (int i = 0; i < 16; i++) {
            float e = __expf(sm[i] - M);
            L += e * sl[i];
            O += e * ((const float*)so[i])[d];
        }
        float kn = g_kp[b * DM + h * DK + d];
        vn       = g_vp[b * DM + h * DK + d];
        prod = sqf[d] * kn;          // q pre-scaled -> new-token score part
    }
#pragma unroll
    for (int off = 16; off; off >>= 1)
        prod += __shfl_xor_sync(0xffffffffu, prod, off);
    if (lane == 0 && warp < 2) red2[warp] = prod;
    __syncthreads();
    if (tid < DK) {
        float s_new = red2[0] + red2[1];
        float Mf = fmaxf(M, s_new);
        float ef = __expf(M - Mf);
        float pn = __expf(s_new - Mf);
        float Lf = L * ef + pn;
        float Of = O * ef + pn * vn;
        g_x[b * DM + h * DK + tid] = Of / Lf;
    }
}

// ---------------------------------------------------------------------------
// inputs (metadata order): 0 q, 1 key_pre, 2 value_pre,
//   3 wq, 4 bq, 5 wk, 6 bk, 7 wv, 8 bv, 9 wo, 10 bo
// output: [32, 1, 1024] fp32
// ---------------------------------------------------------------------------
extern "C" void kernel_launch(void* const* d_in, const int* in_sizes, int n_in,
                              void* d_out, int out_size)
{
    const float* q   = (const float*)d_in[0];
    const float* Kc  = (const float*)d_in[1];
    const float* Vc  = (const float*)d_in[2];
    const float* wq  = (const float*)d_in[3];
    const float* bq  = (const float*)d_in[4];
    const float* wk  = (const float*)d_in[5];
    const float* bk  = (const float*)d_in[6];
    const float* wv  = (const float*)d_in[7];
    const float* bv  = (const float*)d_in[8];
    const float* wo  = (const float*)d_in[9];
    const float* bo  = (const float*)d_in[10];
    float* out = (float*)d_out;

    // q projection only (k/v projections run inside fused_attn, overlapped)
    proj_kernel<<<dim3(DM / 8, 1, 4), 128>>>(0, q, wq, bq, nullptr, 0.125f);

    // Fused: 32 kv-producer CTAs + 512 attention CTAs, single wave
    fused_attn<<<NKV_CTA + NATTN, 256>>>(q, Kc, Vc, wk, bk, wv, bv);

    // Output projection (also resets g_kv_done for the next graph replay)
    proj_kernel<<<dim3(DM / 8, 1, 4), 128>>>(1, nullptr, wo, bo, out, 1.0f);
}

// round 14
// speedup vs baseline: 1.1879x; 1.1879x over previous
#include <cuda_runtime.h>
#include <cstdint>

#define BATCH 32
#define NH    16
#define DK    64
#define DM    1024
#define TC    4096

// Scratch (device globals — no allocation allowed in kernel_launch)
__device__ float g_qp[BATCH * DM];   // scaled query projection
__device__ float g_kp[BATCH * DM];   // new-token key projection
__device__ float g_vp[BATCH * DM];   // new-token value projection
__device__ float g_x [BATCH * DM];   // attention output (pre out-proj)

// Packed dual-FMA (sm_103a FFMA2; PTX-only)
__device__ __forceinline__ void ffma2(unsigned long long& d,
                                      unsigned long long a,
                                      unsigned long long b)
{
    asm("fma.rn.f32x2 %0, %1, %2, %0;" : "+l"(d) : "l"(a), "l"(b));
}
__device__ __forceinline__ float pair_sum(unsigned long long v)
{
    return __uint_as_float((unsigned)v) + __uint_as_float((unsigned)(v >> 32));
}
__device__ __forceinline__ void cp16(uint32_t smem_dst, const float* gsrc)
{
    asm volatile("cp.async.cg.shared.global [%0], [%1], 16;"
                 :: "r"(smem_dst), "l"(gsrc) : "memory");
}

// ---------------------------------------------------------------------------
// GEMV projection, single-wave fully-async: grid (DM/8, nmat, 1), block 128.
// CTA = 8 weight rows x ALL 32 batches. Weights (32KB) staged via cp.async
// (register-free, fully in flight -> 24MB outstanding chip-wide at t=0, so
// the 12.6MB weight stream drains at full HBM BW instead of the ~830GB/s
// register-LDG MLP cap that pinned R7-R12). Act streamed through a 2x16KB
// double buffer, 8 groups of 4 batches, commits pipelined one group ahead.
// smem 64KB -> 3 CTAs/SM -> all 384 (QKV) / 128 (outproj) CTAs resident.
// FFMA2 inner product (R11-proven).
// mode 0: QKV — grid.y selects {wq->g_qp (*qscale), wk->g_kp, wv->g_vp}
// mode 1: out-projection — act = g_x (device symbol), W0/B0 -> out_ext
// ---------------------------------------------------------------------------
__global__ void __launch_bounds__(128)
proj_kernel(int mode,
            const float* __restrict__ act_ext,
            const float* __restrict__ W0, const float* __restrict__ B0,
            const float* __restrict__ W1, const float* __restrict__ B1,
            const float* __restrict__ W2, const float* __restrict__ B2,
            float* __restrict__ out_ext,
            float qscale)
{
    extern __shared__ __align__(16) float smem[];
    float* s_w   = smem;            // 8 rows x DM  = 32 KB
    float* s_act = smem + 8 * DM;   // 2 bufs x 4 batches x DM = 32 KB

    const float* act;
    const float* W;
    const float* bias;
    float* out;
    float scale = 1.0f;

    if (mode == 1) {
        act = g_x;  W = W0; bias = B0; out = out_ext;
    } else {
        act = act_ext;
        if (blockIdx.y == 0)      { W = W0; bias = B0; out = g_qp; scale = qscale; }
        else if (blockIdx.y == 1) { W = W1; bias = B1; out = g_kp; }
        else                      { W = W2; bias = B2; out = g_vp; }
    }

    const int tid  = threadIdx.x;
    const int warp = tid >> 5;
    const int lane = tid & 31;
    const int j0   = blockIdx.x * 8 + warp * 2;     // 2 rows per warp

    const uint32_t swb = (uint32_t)__cvta_generic_to_shared(s_w);
    const uint32_t sab = (uint32_t)__cvta_generic_to_shared(s_act);

    // ---- commit weights (group 0): 2048 x 16B units, 16 per thread ----
    {
        const float* Wbase = W + (size_t)(blockIdx.x * 8) * DM;
#pragma unroll
        for (int i = 0; i < 16; i++) {
            int u = i * 128 + tid;
            cp16(swb + u * 16, Wbase + u * 4);
        }
        asm volatile("cp.async.commit_group;" ::: "memory");
    }

    // act group committer: group g = batches 4g..4g+3 into buffer g&1
#define COMMIT_ACT(g_)                                                       \
    do {                                                                     \
        const float* _src = act + (size_t)((g_) * 4) * DM;                   \
        uint32_t _dst = sab + (((g_) & 1) * 4 * DM) * 4;                     \
        _Pragma("unroll")                                                    \
        for (int _i = 0; _i < 8; _i++) {                                     \
            int _u = _i * 128 + tid;                                         \
            cp16(_dst + _u * 16, _src + _u * 4);                             \
        }                                                                    \
        asm volatile("cp.async.commit_group;" ::: "memory");                 \
    } while (0)

    COMMIT_ACT(0);
    COMMIT_ACT(1);

    const float bias0 = bias[j0], bias1 = bias[j0 + 1];

    // ---- weights arrived (2 act groups may be pending) ----
    asm volatile("cp.async.wait_group 2;" ::: "memory");
    __syncthreads();

    ulonglong2 w[2][8];
#pragma unroll
    for (int r = 0; r < 2; r++)
#pragma unroll
        for (int c = 0; c < 8; c++)
            w[r][c] = *(const ulonglong2*)&s_w[(warp * 2 + r) * DM + c * 128 + lane * 4];

#pragma unroll
    for (int g = 0; g < 8; g++) {
        // A_g arrived when at most 1 later group remains pending (0 for g=7)
        if (g < 7) asm volatile("cp.async.wait_group 1;" ::: "memory");
        else       asm volatile("cp.async.wait_group 0;" ::: "memory");
        __syncthreads();

        const float* sa = s_act + (g & 1) * 4 * DM;
        unsigned long long a2[4][2];
#pragma unroll
        for (int b = 0; b < 4; b++) { a2[b][0] = 0ull; a2[b][1] = 0ull; }

#pragma unroll
        for (int c = 0; c < 8; c++) {
#pragma unroll
            for (int b = 0; b < 4; b++) {
                ulonglong2 x = *(const ulonglong2*)&sa[b * DM + c * 128 + lane * 4];
                ffma2(a2[b][0], x.x, w[0][c].x);
                ffma2(a2[b][0], x.y, w[0][c].y);
                ffma2(a2[b][1], x.x, w[1][c].x);
                ffma2(a2[b][1], x.y, w[1][c].y);
            }
        }

        float a[4][2];
#pragma unroll
        for (int b = 0; b < 4; b++) {
            a[b][0] = pair_sum(a2[b][0]);
            a[b][1] = pair_sum(a2[b][1]);
        }
#pragma unroll
        for (int off = 16; off; off >>= 1) {
#pragma unroll
            for (int b = 0; b < 4; b++) {
                a[b][0] += __shfl_xor_sync(0xffffffffu, a[b][0], off);
                a[b][1] += __shfl_xor_sync(0xffffffffu, a[b][1], off);
            }
        }

        if (lane == 0) {
            const int bb0 = g * 4;
#pragma unroll
            for (int b = 0; b < 4; b++) {
                out[(size_t)(bb0 + b) * DM + j0]     = (a[b][0] + bias0) * scale;
                out[(size_t)(bb0 + b) * DM + j0 + 1] = (a[b][1] + bias1) * scale;
            }
        }

        __syncthreads();                 // all reads of buf (g&1) done
        if (g + 2 < 8) COMMIT_ACT(g + 2);   // refill the freed buffer
    }
#undef COMMIT_ACT
}

// ---------------------------------------------------------------------------
// Flash-decode attention over 4096 cached keys + 1 new token (R7-proven,
// at HBM roofline ~7.2 TB/s — UNCHANGED).
// One CTA per (b,h): 512 CTAs x 256 threads, single wave (4 CTAs/SM).
// float4 / half-warp layout; block-softmax over 4-key blocks per half.
// ---------------------------------------------------------------------------
__global__ void __launch_bounds__(256, 4)
attn_kernel(const float* __restrict__ Kc,
            const float* __restrict__ Vc)
{
    const int bh   = blockIdx.x;       // 0..511
    const int b    = bh >> 4;
    const int h    = bh & 15;
    const int warp = threadIdx.x >> 5;
    const int lane = threadIdx.x & 31;
    const int half = lane >> 4;        // 0 or 1
    const int li   = lane & 15;        // lane within half; dims 4*li..4*li+3

    __shared__ float4 sq[16];          // q, pre-scaled by 1/sqrt(DK)
    __shared__ float  sm[16], sl[16];
    __shared__ float4 so[16][16];

    if (threadIdx.x < 16)
        sq[threadIdx.x] = *(const float4*)(g_qp + b * DM + h * DK + 4 * threadIdx.x);
    __syncthreads();

    const float4 q4 = sq[li];

    const float* Kp = Kc + (size_t)bh * TC * DK + (size_t)half * DK + 4 * li;
    const float* Vp = Vc + (size_t)bh * TC * DK + (size_t)half * DK + 4 * li;

    float  m = -1e30f;
    float  l = 0.0f;
    float4 o = make_float4(0.f, 0.f, 0.f, 0.f);

    const int t0 = warp * (TC / 8);    // 512 keys per warp; 4/half per iter
    for (int t = t0; t < t0 + TC / 8; t += 8) {
        float4 kk[4], vv[4];
#pragma unroll
        for (int i = 0; i < 4; i++)
            kk[i] = __ldcs((const float4*)(Kp + (size_t)(t + 2 * i) * DK));
#pragma unroll
        for (int i = 0; i < 4; i++)
            vv[i] = __ldcs((const float4*)(Vp + (size_t)(t + 2 * i) * DK));

        float s[4];
#pragma unroll
        for (int i = 0; i < 4; i++)
            s[i] = kk[i].x * q4.x + kk[i].y * q4.y + kk[i].z * q4.z + kk[i].w * q4.w;
#pragma unroll
        for (int off = 8; off; off >>= 1)
#pragma unroll
            for (int i = 0; i < 4; i++)
                s[i] += __shfl_xor_sync(0xffffffffu, s[i], off);   // within half

        float bm = fmaxf(fmaxf(s[0], s[1]), fmaxf(s[2], s[3]));
        float mn = fmaxf(m, bm);

        float p[4];
#pragma unroll
        for (int i = 0; i < 4; i++) p[i] = __expf(s[i] - mn);

        float  lp = 0.0f;
        float4 op = make_float4(0.f, 0.f, 0.f, 0.f);
#pragma unroll
        for (int i = 0; i < 4; i++) {
            lp   += p[i];
            op.x += p[i] * vv[i].x;
            op.y += p[i] * vv[i].y;
            op.z += p[i] * vv[i].z;
            op.w += p[i] * vv[i].w;
        }

        float sc = __expf(m - mn);
        l   = l   * sc + lp;
        o.x = o.x * sc + op.x;
        o.y = o.y * sc + op.y;
        o.z = o.z * sc + op.z;
        o.w = o.w * sc + op.w;
        m   = mn;
    }

    // New (appended) token: warp 0 computes the score; half 0 folds it in.
    if (warp == 0) {
        float4 kk = *(const float4*)(g_kp + b * DM + h * DK + 4 * li);
        float4 vv = *(const float4*)(g_vp + b * DM + h * DK + 4 * li);
        float s = kk.x * q4.x + kk.y * q4.y + kk.z * q4.z + kk.w * q4.w;
#pragma unroll
        for (int off = 8; off; off >>= 1)
            s += __shfl_xor_sync(0xffffffffu, s, off);
        if (half == 0) {
            float mn = fmaxf(m, s);
            float sc = __expf(m - mn);
            float p  = __expf(s - mn);
            l   = l   * sc + p;
            o.x = o.x * sc + p * vv.x;
            o.y = o.y * sc + p * vv.y;
            o.z = o.z * sc + p * vv.z;
            o.w = o.w * sc + p * vv.w;
            m   = mn;
        }
    }

    const int idx = warp * 2 + half;   // 16 partial states
    if (li == 0) { sm[idx] = m; sl[idx] = l; }
    so[idx][li] = o;
    __syncthreads();

    // Combine 16 partial states; threads 0..63 each own one output dim.
    if (threadIdx.x < DK) {
        const int d = threadIdx.x;
        float M = sm[0];
#pragma unroll
        for (int i = 1; i < 16; i++) M = fmaxf(M, sm[i]);
        float L = 0.0f, O = 0.0f;
#pragma unroll
        for (int i = 0; i < 16; i++) {
            float e = __expf(sm[i] - M);
            L += e * sl[i];
            O += e * ((const float*)so[i])[d];
        }
        g_x[b * DM + h * DK + d] = O / L;
    }
}

// ---------------------------------------------------------------------------
// inputs (metadata order): 0 q, 1 key_pre, 2 value_pre,
//   3 wq, 4 bq, 5 wk, 6 bk, 7 wv, 8 bv, 9 wo, 10 bo
// output: [32, 1, 1024] fp32
// ---------------------------------------------------------------------------
extern "C" void kernel_launch(void* const* d_in, const int* in_sizes, int n_in,
                              void* d_out, int out_size)
{
    const float* q   = (const float*)d_in[0];
    const float* Kc  = (const float*)d_in[1];
    const float* Vc  = (const float*)d_in[2];
    const float* wq  = (const float*)d_in[3];
    const float* bq  = (const float*)d_in[4];
    const float* wk  = (const float*)d_in[5];
    const float* bk  = (const float*)d_in[6];
    const float* wv  = (const float*)d_in[7];
    const float* bv  = (const float*)d_in[8];
    const float* wo  = (const float*)d_in[9];
    const float* bo  = (const float*)d_in[10];
    float* out = (float*)d_out;

    const float qscale = 0.125f;  // 1/sqrt(DK)
    const int smem_bytes = 16 * DM * (int)sizeof(float);   // 64 KB

    // Host-side attribute set (idempotent, allocation-free, capture-safe).
    cudaFuncSetAttribute(proj_kernel,
                         cudaFuncAttributeMaxDynamicSharedMemorySize, smem_bytes);

    // QKV projections: 384 CTAs, all resident, weights fully async
    proj_kernel<<<dim3(DM / 8, 3, 1), 128, smem_bytes>>>(
        0, q, wq, bq, wk, bk, wv, bv, nullptr, qscale);

    // Flash-decode attention over the cache + appended token (single wave)
    attn_kernel<<<BATCH * NH, 256>>>(Kc, Vc);

    // Output projection: 128 CTAs, reads g_x via device symbol
    proj_kernel<<<dim3(DM / 8, 1, 1), 128, smem_bytes>>>(
        1, nullptr, wo, bo, nullptr, nullptr, nullptr, nullptr, out, 1.0f);
}

// round 15
// speedup vs baseline: 1.1925x; 1.0038x over previous
#include <cuda_runtime.h>
#include <cstdint>

#define BATCH 32
#define NH    16
#define DK    64
#define DM    1024
#define TC    4096

// Scratch (device globals — no allocation allowed in kernel_launch)
__device__ float g_qp[BATCH * DM];   // scaled query projection
__device__ float g_kp[BATCH * DM];   // new-token key projection
__device__ float g_vp[BATCH * DM];   // new-token value projection
__device__ float g_x [BATCH * DM];   // attention output (pre out-proj)

// Packed dual-FMA (sm_103a FFMA2; PTX-only)
__device__ __forceinline__ void ffma2(unsigned long long& d,
                                      unsigned long long a,
                                      unsigned long long b)
{
    asm("fma.rn.f32x2 %0, %1, %2, %0;" : "+l"(d) : "l"(a), "l"(b));
}
__device__ __forceinline__ float pair_sum(unsigned long long v)
{
    return __uint_as_float((unsigned)v) + __uint_as_float((unsigned)(v >> 32));
}

// ---------------------------------------------------------------------------
// QKV projection (R11-proven, 15.4us): grid (DM/8, 3, 4), block 128.
// CTA owns 8 rows x 8 batches as two cp.async-staged groups of 4; FFMA2.
// grid.y selects {wq->g_qp (*qscale), wk->g_kp, wv->g_vp}.
// ---------------------------------------------------------------------------
__global__ void __launch_bounds__(128)
qkv_kernel(const float* __restrict__ act,
           const float* __restrict__ W0, const float* __restrict__ B0,
           const float* __restrict__ W1, const float* __restrict__ B1,
           const float* __restrict__ W2, const float* __restrict__ B2,
           float qscale)
{
    const float* W;
    const float* bias;
    float* out;
    float scale = 1.0f;
    if (blockIdx.y == 0)      { W = W0; bias = B0; out = g_qp; scale = qscale; }
    else if (blockIdx.y == 1) { W = W1; bias = B1; out = g_kp; }
    else                      { W = W2; bias = B2; out = g_vp; }

    const int warp = threadIdx.x >> 5;
    const int lane = threadIdx.x & 31;
    const int j0   = (blockIdx.x * 4 + warp) * 2;
    const int b0   = blockIdx.z * 8;

    __shared__ __align__(16) float s_act[2][4 * DM];

    {
        const float* src0 = act + (size_t)b0 * DM;
        const float* src1 = act + (size_t)(b0 + 4) * DM;
        uint32_t sb0 = (uint32_t)__cvta_generic_to_shared(s_act[0]);
        uint32_t sb1 = (uint32_t)__cvta_generic_to_shared(s_act[1]);
#pragma unroll
        for (int i = 0; i < 8; i++) {
            int u = i * 128 + threadIdx.x;
            asm volatile("cp.async.cg.shared.global [%0], [%1], 16;"
                         :: "r"(sb0 + u * 16), "l"(src0 + u * 4) : "memory");
        }
        asm volatile("cp.async.commit_group;" ::: "memory");
#pragma unroll
        for (int i = 0; i < 8; i++) {
            int u = i * 128 + threadIdx.x;
            asm volatile("cp.async.cg.shared.global [%0], [%1], 16;"
                         :: "r"(sb1 + u * 16), "l"(src1 + u * 4) : "memory");
        }
        asm volatile("cp.async.commit_group;" ::: "memory");
    }

    ulonglong2 w[2][8];
#pragma unroll
    for (int r = 0; r < 2; r++) {
        const float* Wr = W + (size_t)(j0 + r) * DM;
#pragma unroll
        for (int c = 0; c < 8; c++)
            w[r][c] = *(const ulonglong2*)(Wr + c * 128 + lane * 4);
    }
    const float bias0 = bias[j0], bias1 = bias[j0 + 1];

    asm volatile("cp.async.wait_group 1;" ::: "memory");
    __syncthreads();

#pragma unroll
    for (int g = 0; g < 2; g++) {
        const float* sa = s_act[g];
        unsigned long long a2[4][2];
#pragma unroll
        for (int b = 0; b < 4; b++) { a2[b][0] = 0ull; a2[b][1] = 0ull; }

#pragma unroll
        for (int c = 0; c < 8; c++) {
#pragma unroll
            for (int b = 0; b < 4; b++) {
                ulonglong2 x = *(const ulonglong2*)&sa[b * DM + c * 128 + lane * 4];
                ffma2(a2[b][0], x.x, w[0][c].x);
                ffma2(a2[b][0], x.y, w[0][c].y);
                ffma2(a2[b][1], x.x, w[1][c].x);
                ffma2(a2[b][1], x.y, w[1][c].y);
            }
        }

        float a[4][2];
#pragma unroll
        for (int b = 0; b < 4; b++) {
            a[b][0] = pair_sum(a2[b][0]);
            a[b][1] = pair_sum(a2[b][1]);
        }
#pragma unroll
        for (int off = 16; off; off >>= 1) {
#pragma unroll
            for (int b = 0; b < 4; b++) {
                a[b][0] += __shfl_xor_sync(0xffffffffu, a[b][0], off);
                a[b][1] += __shfl_xor_sync(0xffffffffu, a[b][1], off);
            }
        }

        if (lane == 0) {
            const int bb0 = b0 + g * 4;
#pragma unroll
            for (int b = 0; b < 4; b++) {
                out[(size_t)(bb0 + b) * DM + j0]     = (a[b][0] + bias0) * scale;
                out[(size_t)(bb0 + b) * DM + j0 + 1] = (a[b][1] + bias1) * scale;
            }
        }
        if (g == 0) {
            asm volatile("cp.async.wait_group 0;" ::: "memory");
            __syncthreads();
        }
    }
}

// ---------------------------------------------------------------------------
// Flash-decode attention (R7-proven, HBM roofline) + PDL: launch overlaps the
// qkv tail; gridDependencySynchronize before reading g_qp.
// One CTA per (b,h): 512 CTAs x 256 threads, single wave (4 CTAs/SM).
// ---------------------------------------------------------------------------
__global__ void __launch_bounds__(256, 4)
attn_kernel(const float* __restrict__ Kc,
            const float* __restrict__ Vc)
{
    cudaGridDependencySynchronize();   // wait for qkv writes (g_qp/g_kp/g_vp)

    const int bh   = blockIdx.x;
    const int b    = bh >> 4;
    const int h    = bh & 15;
    const int warp = threadIdx.x >> 5;
    const int lane = threadIdx.x & 31;
    const int half = lane >> 4;
    const int li   = lane & 15;

    __shared__ float4 sq[16];
    __shared__ float  sm[16], sl[16];
    __shared__ float4 so[16][16];

    if (threadIdx.x < 16)
        sq[threadIdx.x] = *(const float4*)(g_qp + b * DM + h * DK + 4 * threadIdx.x);
    __syncthreads();

    const float4 q4 = sq[li];

    const float* Kp = Kc + (size_t)bh * TC * DK + (size_t)half * DK + 4 * li;
    const float* Vp = Vc + (size_t)bh * TC * DK + (size_t)half * DK + 4 * li;

    float  m = -1e30f;
    float  l = 0.0f;
    float4 o = make_float4(0.f, 0.f, 0.f, 0.f);

    const int t0 = warp * (TC / 8);
    for (int t = t0; t < t0 + TC / 8; t += 8) {
        float4 kk[4], vv[4];
#pragma unroll
        for (int i = 0; i < 4; i++)
            kk[i] = __ldcs((const float4*)(Kp + (size_t)(t + 2 * i) * DK));
#pragma unroll
        for (int i = 0; i < 4; i++)
            vv[i] = __ldcs((const float4*)(Vp + (size_t)(t + 2 * i) * DK));

        float s[4];
#pragma unroll
        for (int i = 0; i < 4; i++)
            s[i] = kk[i].x * q4.x + kk[i].y * q4.y + kk[i].z * q4.z + kk[i].w * q4.w;
#pragma unroll
        for (int off = 8; off; off >>= 1)
#pragma unroll
            for (int i = 0; i < 4; i++)
                s[i] += __shfl_xor_sync(0xffffffffu, s[i], off);

        float bm = fmaxf(fmaxf(s[0], s[1]), fmaxf(s[2], s[3]));
        float mn = fmaxf(m, bm);

        float p[4];
#pragma unroll
        for (int i = 0; i < 4; i++) p[i] = __expf(s[i] - mn);

        float  lp = 0.0f;
        float4 op = make_float4(0.f, 0.f, 0.f, 0.f);
#pragma unroll
        for (int i = 0; i < 4; i++) {
            lp   += p[i];
            op.x += p[i] * vv[i].x;
            op.y += p[i] * vv[i].y;
            op.z += p[i] * vv[i].z;
            op.w += p[i] * vv[i].w;
        }

        float sc = __expf(m - mn);
        l   = l   * sc + lp;
        o.x = o.x * sc + op.x;
        o.y = o.y * sc + op.y;
        o.z = o.z * sc + op.z;
        o.w = o.w * sc + op.w;
        m   = mn;
    }

    if (warp == 0) {
        float4 kk = *(const float4*)(g_kp + b * DM + h * DK + 4 * li);
        float4 vv = *(const float4*)(g_vp + b * DM + h * DK + 4 * li);
        float s = kk.x * q4.x + kk.y * q4.y + kk.z * q4.z + kk.w * q4.w;
#pragma unroll
        for (int off = 8; off; off >>= 1)
            s += __shfl_xor_sync(0xffffffffu, s, off);
        if (half == 0) {
            float mn = fmaxf(m, s);
            float sc = __expf(m - mn);
            float p  = __expf(s - mn);
            l   = l   * sc + p;
            o.x = o.x * sc + p * vv.x;
            o.y = o.y * sc + p * vv.y;
            o.z = o.z * sc + p * vv.z;
            o.w = o.w * sc + p * vv.w;
            m   = mn;
        }
    }

    const int idx = warp * 2 + half;
    if (li == 0) { sm[idx] = m; sl[idx] = l; }
    so[idx][li] = o;
    __syncthreads();

    if (threadIdx.x < DK) {
        const int d = threadIdx.x;
        float M = sm[0];
#pragma unroll
        for (int i = 1; i < 16; i++) M = fmaxf(M, sm[i]);
        float L = 0.0f, O = 0.0f;
#pragma unroll
        for (int i = 0; i < 16; i++) {
            float e = __expf(sm[i] - M);
            L += e * sl[i];
            O += e * ((const float*)so[i])[d];
        }
        g_x[b * DM + h * DK + d] = O / L;
    }
}

// ---------------------------------------------------------------------------
// Output projection + PDL: grid (DM/8, 1, 4) = 512 CTAs, block 128.
// PREAMBLE (runs while attention drains): load wo rows into registers + bias.
// Then gridDependencySynchronize (g_x ready), stage act via cp.async, compute.
// ---------------------------------------------------------------------------
__global__ void __launch_bounds__(128)
outproj_kernel(const float* __restrict__ wo,
               const float* __restrict__ bo,
               float* __restrict__ out)
{
    const int warp = threadIdx.x >> 5;
    const int lane = threadIdx.x & 31;
    const int j0   = (blockIdx.x * 4 + warp) * 2;
    const int b0   = blockIdx.z * 8;

    __shared__ __align__(16) float s_act[2][4 * DM];

    // ---- preamble: weights + bias (input-constant, safe before sync) ----
    ulonglong2 w[2][8];
#pragma unroll
    for (int r = 0; r < 2; r++) {
        const float* Wr = wo + (size_t)(j0 + r) * DM;
#pragma unroll
        for (int c = 0; c < 8; c++)
            w[r][c] = *(const ulonglong2*)(Wr + c * 128 + lane * 4);
    }
    const float bias0 = bo[j0], bias1 = bo[j0 + 1];

    cudaGridDependencySynchronize();   // g_x now complete & visible

    {
        const float* src0 = g_x + (size_t)b0 * DM;
        const float* src1 = g_x + (size_t)(b0 + 4) * DM;
        uint32_t sb0 = (uint32_t)__cvta_generic_to_shared(s_act[0]);
        uint32_t sb1 = (uint32_t)__cvta_generic_to_shared(s_act[1]);
#pragma unroll
        for (int i = 0; i < 8; i++) {
            int u = i * 128 + threadIdx.x;
            asm volatile("cp.async.cg.shared.global [%0], [%1], 16;"
                         :: "r"(sb0 + u * 16), "l"(src0 + u * 4) : "memory");
        }
        asm volatile("cp.async.commit_group;" ::: "memory");
#pragma unroll
        for (int i = 0; i < 8; i++) {
            int u = i * 128 + threadIdx.x;
            asm volatile("cp.async.cg.shared.global [%0], [%1], 16;"
                         :: "r"(sb1 + u * 16), "l"(src1 + u * 4) : "memory");
        }
        asm volatile("cp.async.commit_group;" ::: "memory");
    }

    asm volatile("cp.async.wait_group 1;" ::: "memory");
    __syncthreads();

#pragma unroll
    for (int g = 0; g < 2; g++) {
        const float* sa = s_act[g];
        unsigned long long a2[4][2];
#pragma unroll
        for (int b = 0; b < 4; b++) { a2[b][0] = 0ull; a2[b][1] = 0ull; }

#pragma unroll
        for (int c = 0; c < 8; c++) {
#pragma unroll
            for (int b = 0; b < 4; b++) {
                ulonglong2 x = *(const ulonglong2*)&sa[b * DM + c * 128 + lane * 4];
                ffma2(a2[b][0], x.x, w[0][c].x);
                ffma2(a2[b][0], x.y, w[0][c].y);
                ffma2(a2[b][1], x.x, w[1][c].x);
                ffma2(a2[b][1], x.y, w[1][c].y);
            }
        }

        float a[4][2];
#pragma unroll
        for (int b = 0; b < 4; b++) {
            a[b][0] = pair_sum(a2[b][0]);
            a[b][1] = pair_sum(a2[b][1]);
        }
#pragma unroll
        for (int off = 16; off; off >>= 1) {
#pragma unroll
            for (int b = 0; b < 4; b++) {
                a[b][0] += __shfl_xor_sync(0xffffffffu, a[b][0], off);
                a[b][1] += __shfl_xor_sync(0xffffffffu, a[b][1], off);
            }
        }

        if (lane == 0) {
            const int bb0 = b0 + g * 4;
#pragma unroll
            for (int b = 0; b < 4; b++) {
                out[(size_t)(bb0 + b) * DM + j0]     = a[b][0] + bias0;
                out[(size_t)(bb0 + b) * DM + j0 + 1] = a[b][1] + bias1;
            }
        }
        if (g == 0) {
            asm volatile("cp.async.wait_group 0;" ::: "memory");
            __syncthreads();
        }
    }
}

// ---------------------------------------------------------------------------
// inputs (metadata order): 0 q, 1 key_pre, 2 value_pre,
//   3 wq, 4 bq, 5 wk, 6 bk, 7 wv, 8 bv, 9 wo, 10 bo
// output: [32, 1, 1024] fp32
// ---------------------------------------------------------------------------
extern "C" void kernel_launch(void* const* d_in, const int* in_sizes, int n_in,
                              void* d_out, int out_size)
{
    const float* q   = (const float*)d_in[0];
    const float* Kc  = (const float*)d_in[1];
    const float* Vc  = (const float*)d_in[2];
    const float* wq  = (const float*)d_in[3];
    const float* bq  = (const float*)d_in[4];
    const float* wk  = (const float*)d_in[5];
    const float* bk  = (const float*)d_in[6];
    const float* wv  = (const float*)d_in[7];
    const float* bv  = (const float*)d_in[8];
    const float* wo  = (const float*)d_in[9];
    const float* bo  = (const float*)d_in[10];
    float* out = (float*)d_out;

    const float qscale = 0.125f;  // 1/sqrt(DK)

    // 1) QKV projections (plain launch)
    qkv_kernel<<<dim3(DM / 8, 3, 4), 128>>>(q, wq, bq, wk, bk, wv, bv, qscale);

    // PDL attribute: allow the dependent kernel to launch/overlap the tail of
    // the preceding one; device-side gridDependencySynchronize() gates reads.
    cudaLaunchAttribute pdl[1];
    pdl[0].id = cudaLaunchAttributeProgrammaticStreamSerialization;
    pdl[0].val.programmaticStreamSerializationAllowed = 1;

    // 2) Attention (PDL after qkv)
    {
        cudaLaunchConfig_t cfg = {};
        cfg.gridDim  = dim3(BATCH * NH, 1, 1);
        cfg.blockDim = dim3(256, 1, 1);
        cfg.dynamicSmemBytes = 0;
        cfg.stream = 0;
        cfg.attrs = pdl;
        cfg.numAttrs = 1;
        cudaLaunchKernelEx(&cfg, attn_kernel, Kc, Vc);
    }

    // 3) Output projection (PDL after attention; weight preamble overlaps
    //    the attention drain window)
    {
        cudaLaunchConfig_t cfg = {};
        cfg.gridDim  = dim3(DM / 8, 1, 4);
        cfg.blockDim = dim3(128, 1, 1);
        cfg.dynamicSmemBytes = 0;
        cfg.stream = 0;
        cfg.attrs = pdl;
        cfg.numAttrs = 1;
        cudaLaunchKernelEx(&cfg, outproj_kernel, wo, bo, out);
    }
}

// round 16
// speedup vs baseline: 1.2091x; 1.0140x over previous
#include <cuda_runtime.h>
#include <cstdint>

#define BATCH 32
#define NH    16
#define DK    64
#define DM    1024
#define TC    4096

// Scratch (device globals — no allocation allowed in kernel_launch)
__device__ float g_kp[BATCH * DM];   // new-token key projection
__device__ float g_vp[BATCH * DM];   // new-token value projection
__device__ float g_x [BATCH * DM];   // attention output (pre out-proj)

// Packed dual-FMA (sm_103a FFMA2; PTX-only)
__device__ __forceinline__ void ffma2(unsigned long long& d,
                                      unsigned long long a,
                                      unsigned long long b)
{
    asm("fma.rn.f32x2 %0, %1, %2, %0;" : "+l"(d) : "l"(a), "l"(b));
}
__device__ __forceinline__ float pair_sum(unsigned long long v)
{
    return __uint_as_float((unsigned)v) + __uint_as_float((unsigned)(v >> 32));
}

// ---------------------------------------------------------------------------
// k/v projection ONLY: grid (DM/8, 2, 2) = 512 CTAs (single wave), block 128.
// CTA owns 8 rows x 16 batches as four cp.async act groups of 4 (2-buf
// pipeline); FFMA2 inner product (R11-proven body).
// Calls cudaTriggerProgrammaticLaunchCompletion() at entry so the PDL-chained
// attention kernel can launch & co-schedule immediately — this kernel's
// ~11us runs inside attention's ~149us HBM stream instead of in front of it.
// ---------------------------------------------------------------------------
__global__ void __launch_bounds__(128)
kv_kernel(const float* __restrict__ act,
          const float* __restrict__ Wk, const float* __restrict__ Bk,
          const float* __restrict__ Wv, const float* __restrict__ Bv)
{
    if (threadIdx.x == 0) cudaTriggerProgrammaticLaunchCompletion();

    const float* W    = (blockIdx.y == 0) ? Wk : Wv;
    const float* bias = (blockIdx.y == 0) ? Bk : Bv;
    float* out        = (blockIdx.y == 0) ? g_kp : g_vp;

    const int tid  = threadIdx.x;
    const int warp = tid >> 5;
    const int lane = tid & 31;
    const int j0   = (blockIdx.x * 4 + warp) * 2;
    const int b0   = blockIdx.z * 16;               // 16 batches per z-slice

    __shared__ __align__(16) float s_act[2][4 * DM];

#define COMMIT_ACT(g_)                                                       \
    do {                                                                     \
        const float* _src = act + (size_t)(b0 + (g_) * 4) * DM;              \
        uint32_t _dst = (uint32_t)__cvta_generic_to_shared(s_act[(g_) & 1]); \
        _Pragma("unroll")                                                    \
        for (int _i = 0; _i < 8; _i++) {                                     \
            int _u = _i * 128 + tid;                                         \
            asm volatile("cp.async.cg.shared.global [%0], [%1], 16;"         \
                         :: "r"(_dst + _u * 16), "l"(_src + _u * 4)          \
                         : "memory");                                        \
        }                                                                    \
        asm volatile("cp.async.commit_group;" ::: "memory");                 \
    } while (0)

    COMMIT_ACT(0);
    COMMIT_ACT(1);

    ulonglong2 w[2][8];
#pragma unroll
    for (int r = 0; r < 2; r++) {
        const float* Wr = W + (size_t)(j0 + r) * DM;
#pragma unroll
        for (int c = 0; c < 8; c++)
            w[r][c] = *(const ulonglong2*)(Wr + c * 128 + lane * 4);
    }
    const float bias0 = bias[j0], bias1 = bias[j0 + 1];

#pragma unroll
    for (int g = 0; g < 4; g++) {
        if (g < 3) asm volatile("cp.async.wait_group 1;" ::: "memory");
        else       asm volatile("cp.async.wait_group 0;" ::: "memory");
        __syncthreads();

        const float* sa = s_act[g & 1];
        unsigned long long a2[4][2];
#pragma unroll
        for (int b = 0; b < 4; b++) { a2[b][0] = 0ull; a2[b][1] = 0ull; }

#pragma unroll
        for (int c = 0; c < 8; c++) {
#pragma unroll
            for (int b = 0; b < 4; b++) {
                ulonglong2 x = *(const ulonglong2*)&sa[b * DM + c * 128 + lane * 4];
                ffma2(a2[b][0], x.x, w[0][c].x);
                ffma2(a2[b][0], x.y, w[0][c].y);
                ffma2(a2[b][1], x.x, w[1][c].x);
                ffma2(a2[b][1], x.y, w[1][c].y);
            }
        }

        float a[4][2];
#pragma unroll
        for (int b = 0; b < 4; b++) {
            a[b][0] = pair_sum(a2[b][0]);
            a[b][1] = pair_sum(a2[b][1]);
        }
#pragma unroll
        for (int off = 16; off; off >>= 1) {
#pragma unroll
            for (int b = 0; b < 4; b++) {
                a[b][0] += __shfl_xor_sync(0xffffffffu, a[b][0], off);
                a[b][1] += __shfl_xor_sync(0xffffffffu, a[b][1], off);
            }
        }

        if (lane == 0) {
            const int bb0 = b0 + g * 4;
#pragma unroll
            for (int b = 0; b < 4; b++) {
                out[(size_t)(bb0 + b) * DM + j0]     = a[b][0] + bias0;
                out[(size_t)(bb0 + b) * DM + j0 + 1] = a[b][1] + bias1;
            }
        }

        if (g + 2 < 4) {
            __syncthreads();        // all reads of buf (g&1) done
            COMMIT_ACT(g + 2);
        }
    }
#undef COMMIT_ACT
}

// ---------------------------------------------------------------------------
// Flash-decode attention, now self-contained for q:
//  1) prologue: each CTA computes its own 64 q-proj outputs from q[b] and
//     wq rows h*64..h*64+63 (8 rows/warp; wq L2-deduped across the 32 CTAs
//     sharing h) — NO dependency on any prior kernel for the main stream.
//  2) stream 4096 cached keys (R7-proven block-softmax body, HBM roofline).
//  3) cudaGridDependencySynchronize() only at the END, before the appended
//     token reads g_kp/g_vp (kv kernel finished ~130us earlier).
// One CTA per (b,h): 512 CTAs x 256 threads, single wave (4 CTAs/SM).
// ---------------------------------------------------------------------------
__global__ void __launch_bounds__(256, 4)
attn_kernel(const float* __restrict__ q,
            const float* __restrict__ wq,
            const float* __restrict__ bq,
            const float* __restrict__ Kc,
            const float* __restrict__ Vc)
{
    const int bh   = blockIdx.x;       // 0..511
    const int b    = bh >> 4;
    const int h    = bh & 15;
    const int warp = threadIdx.x >> 5;
    const int lane = threadIdx.x & 31;
    const int half = lane >> 4;
    const int li   = lane & 15;

    __shared__ __align__(16) float sqf[DK];
    __shared__ float  sm[16], sl[16];
    __shared__ float4 so[16][16];
    __shared__ float  red2[2];

    // ---- q-projection prologue: warp computes rows h*64+warp*8 .. +7 ----
    {
        const float* qb = q + (size_t)b * DM;
        const float* Wq = wq + (size_t)(h * DK + warp * 8) * DM;
        float acc[8];
#pragma unroll
        for (int r = 0; r < 8; r++) acc[r] = 0.0f;
#pragma unroll
        for (int c = 0; c < 8; c++) {
            float4 x = *(const float4*)(qb + c * 128 + lane * 4);
#pragma unroll
            for (int r = 0; r < 8; r++) {
                float4 wv4 = *(const float4*)(Wq + (size_t)r * DM + c * 128 + lane * 4);
                acc[r] += x.x * wv4.x + x.y * wv4.y + x.z * wv4.z + x.w * wv4.w;
            }
        }
#pragma unroll
        for (int off = 16; off; off >>= 1)
#pragma unroll
            for (int r = 0; r < 8; r++)
                acc[r] += __shfl_xor_sync(0xffffffffu, acc[r], off);
        if (lane == 0) {
#pragma unroll
            for (int r = 0; r < 8; r++)
                sqf[warp * 8 + r] = (acc[r] + bq[h * DK + warp * 8 + r]) * 0.125f;
        }
    }
    __syncthreads();

    const float4 q4 = *(const float4*)&sqf[4 * li];

    const float* Kp = Kc + (size_t)bh * TC * DK + (size_t)half * DK + 4 * li;
    const float* Vp = Vc + (size_t)bh * TC * DK + (size_t)half * DK + 4 * li;

    float  m = -1e30f;
    float  l = 0.0f;
    float4 o = make_float4(0.f, 0.f, 0.f, 0.f);

    const int t0 = warp * (TC / 8);
    for (int t = t0; t < t0 + TC / 8; t += 8) {
        float4 kk[4], vv[4];
#pragma unroll
        for (int i = 0; i < 4; i++)
            kk[i] = __ldcs((const float4*)(Kp + (size_t)(t + 2 * i) * DK));
#pragma unroll
        for (int i = 0; i < 4; i++)
            vv[i] = __ldcs((const float4*)(Vp + (size_t)(t + 2 * i) * DK));

        float s[4];
#pragma unroll
        for (int i = 0; i < 4; i++)
            s[i] = kk[i].x * q4.x + kk[i].y * q4.y + kk[i].z * q4.z + kk[i].w * q4.w;
#pragma unroll
        for (int off = 8; off; off >>= 1)
#pragma unroll
            for (int i = 0; i < 4; i++)
                s[i] += __shfl_xor_sync(0xffffffffu, s[i], off);

        float bm = fmaxf(fmaxf(s[0], s[1]), fmaxf(s[2], s[3]));
        float mn = fmaxf(m, bm);

        float p[4];
#pragma unroll
        for (int i = 0; i < 4; i++) p[i] = __expf(s[i] - mn);

        float  lp = 0.0f;
        float4 op = make_float4(0.f, 0.f, 0.f, 0.f);
#pragma unroll
        for (int i = 0; i < 4; i++) {
            lp   += p[i];
            op.x += p[i] * vv[i].x;
            op.y += p[i] * vv[i].y;
            op.z += p[i] * vv[i].z;
            op.w += p[i] * vv[i].w;
        }

        float sc = __expf(m - mn);
        l   = l   * sc + lp;
        o.x = o.x * sc + op.x;
        o.y = o.y * sc + op.y;
        o.z = o.z * sc + op.z;
        o.w = o.w * sc + op.w;
        m   = mn;
    }

    // Publish 16 partial states, then wait for the kv kernel (finished long
    // ago) before touching g_kp/g_vp.
    const int idx = warp * 2 + half;
    if (li == 0) { sm[idx] = m; sl[idx] = l; }
    so[idx][li] = o;
    cudaGridDependencySynchronize();
    __syncthreads();

    // Merge 16 states + appended token (R13-verified epilogue).
    float prod = 0.0f, M = -1e30f, L = 0.0f, O = 0.0f, vn = 0.0f;
    if (threadIdx.x < DK) {
        const int d = threadIdx.x;
        M = sm[0];
#pragma unroll
        for (int i = 1; i < 16; i++) M = fmaxf(M, sm[i]);
#pragma unroll
        for (int i = 0; i < 16; i++) {
            float e = __expf(sm[i] - M);
            L += e * sl[i];
            O += e * ((const float*)so[i])[d];
        }
        float kn = g_kp[b * DM + h * DK + d];
        vn       = g_vp[b * DM + h * DK + d];
        prod = sqf[d] * kn;          // q pre-scaled -> new-token score part
    }
#pragma unroll
    for (int off = 16; off; off >>= 1)
        prod += __shfl_xor_sync(0xffffffffu, prod, off);
    if (lane == 0 && warp < 2) red2[warp] = prod;
    __syncthreads();
    if (threadIdx.x < DK) {
        float s_new = red2[0] + red2[1];
        float Mf = fmaxf(M, s_new);
        float ef = __expf(M - Mf);
        float pn = __expf(s_new - Mf);
        float Lf = L * ef + pn;
        float Of = O * ef + pn * vn;
        g_x[b * DM + h * DK + threadIdx.x] = Of / Lf;
    }
}

// ---------------------------------------------------------------------------
// Output projection + PDL (R15-proven): grid (DM/8, 1, 4), block 128.
// Weight preamble overlaps the attention drain; sync, then cp.async act.
// ---------------------------------------------------------------------------
__global__ void __launch_bounds__(128)
outproj_kernel(const float* __restrict__ wo,
               const float* __restrict__ bo,
               float* __restrict__ out)
{
    const int warp = threadIdx.x >> 5;
    const int lane = threadIdx.x & 31;
    const int j0   = (blockIdx.x * 4 + warp) * 2;
    const int b0   = blockIdx.z * 8;

    __shared__ __align__(16) float s_act[2][4 * DM];

    ulonglong2 w[2][8];
#pragma unroll
    for (int r = 0; r < 2; r++) {
        const float* Wr = wo + (size_t)(j0 + r) * DM;
#pragma unroll
        for (int c = 0; c < 8; c++)
            w[r][c] = *(const ulonglong2*)(Wr + c * 128 + lane * 4);
    }
    const float bias0 = bo[j0], bias1 = bo[j0 + 1];

    cudaGridDependencySynchronize();   // g_x complete & visible

    {
        const float* src0 = g_x + (size_t)b0 * DM;
        const float* src1 = g_x + (size_t)(b0 + 4) * DM;
        uint32_t sb0 = (uint32_t)__cvta_generic_to_shared(s_act[0]);
        uint32_t sb1 = (uint32_t)__cvta_generic_to_shared(s_act[1]);
#pragma unroll
        for (int i = 0; i < 8; i++) {
            int u = i * 128 + threadIdx.x;
            asm volatile("cp.async.cg.shared.global [%0], [%1], 16;"
                         :: "r"(sb0 + u * 16), "l"(src0 + u * 4) : "memory");
        }
        asm volatile("cp.async.commit_group;" ::: "memory");
#pragma unroll
        for (int i = 0; i < 8; i++) {
            int u = i * 128 + threadIdx.x;
            asm volatile("cp.async.cg.shared.global [%0], [%1], 16;"
                         :: "r"(sb1 + u * 16), "l"(src1 + u * 4) : "memory");
        }
        asm volatile("cp.async.commit_group;" ::: "memory");
    }

    asm volatile("cp.async.wait_group 1;" ::: "memory");
    __syncthreads();

#pragma unroll
    for (int g = 0; g < 2; g++) {
        const float* sa = s_act[g];
        unsigned long long a2[4][2];
#pragma unroll
        for (int b = 0; b < 4; b++) { a2[b][0] = 0ull; a2[b][1] = 0ull; }

#pragma unroll
        for (int c = 0; c < 8; c++) {
#pragma unroll
            for (int b = 0; b < 4; b++) {
                ulonglong2 x = *(const ulonglong2*)&sa[b * DM + c * 128 + lane * 4];
                ffma2(a2[b][0], x.x, w[0][c].x);
                ffma2(a2[b][0], x.y, w[0][c].y);
                ffma2(a2[b][1], x.x, w[1][c].x);
                ffma2(a2[b][1], x.y, w[1][c].y);
            }
        }

        float a[4][2];
#pragma unroll
        for (int b = 0; b < 4; b++) {
            a[b][0] = pair_sum(a2[b][0]);
            a[b][1] = pair_sum(a2[b][1]);
        }
#pragma unroll
        for (int off = 16; off; off >>= 1) {
#pragma unroll
            for (int b = 0; b < 4; b++) {
                a[b][0] += __shfl_xor_sync(0xffffffffu, a[b][0], off);
                a[b][1] += __shfl_xor_sync(0xffffffffu, a[b][1], off);
            }
        }

        if (lane == 0) {
            const int bb0 = b0 + g * 4;
#pragma unroll
            for (int b = 0; b < 4; b++) {
                out[(size_t)(bb0 + b) * DM + j0]     = a[b][0] + bias0;
                out[(size_t)(bb0 + b) * DM + j0 + 1] = a[b][1] + bias1;
            }
        }
        if (g == 0) {
            asm volatile("cp.async.wait_group 0;" ::: "memory");
            __syncthreads();
        }
    }
}

// ---------------------------------------------------------------------------
// inputs (metadata order): 0 q, 1 key_pre, 2 value_pre,
//   3 wq, 4 bq, 5 wk, 6 bk, 7 wv, 8 bv, 9 wo, 10 bo
// output: [32, 1, 1024] fp32
// ---------------------------------------------------------------------------
extern "C" void kernel_launch(void* const* d_in, const int* in_sizes, int n_in,
                              void* d_out, int out_size)
{
    const float* q   = (const float*)d_in[0];
    const float* Kc  = (const float*)d_in[1];
    const float* Vc  = (const float*)d_in[2];
    const float* wq  = (const float*)d_in[3];
    const float* bq  = (const float*)d_in[4];
    const float* wk  = (const float*)d_in[5];
    const float* bk  = (const float*)d_in[6];
    const float* wv  = (const float*)d_in[7];
    const float* bv  = (const float*)d_in[8];
    const float* wo  = (const float*)d_in[9];
    const float* bo  = (const float*)d_in[10];
    float* out = (float*)d_out;

    // 1) k/v projections; triggers programmatic completion at entry so the
    //    attention kernel launches & overlaps immediately.
    kv_kernel<<<dim3(DM / 8, 2, 2), 128>>>(q, wk, bk, wv, bv);

    cudaLaunchAttribute pdl[1];
    pdl[0].id = cudaLaunchAttributeProgrammaticStreamSerialization;
    pdl[0].val.programmaticStreamSerializationAllowed = 1;

    // 2) Attention (PDL): self-contained q-proj; syncs on kv only at the end.
    {
        cudaLaunchConfig_t cfg = {};
        cfg.gridDim  = dim3(BATCH * NH, 1, 1);
        cfg.blockDim = dim3(256, 1, 1);
        cfg.stream = 0;
        cfg.attrs = pdl;
        cfg.numAttrs = 1;
        cudaLaunchKernelEx(&cfg, attn_kernel, q, wq, bq, Kc, Vc);
    }

    // 3) Output projection (PDL): weight preamble overlaps attention drain.
    {
        cudaLaunchConfig_t cfg = {};
        cfg.gridDim  = dim3(DM / 8, 1, 4);
        cfg.blockDim = dim3(128, 1, 1);
        cfg.stream = 0;
        cfg.attrs = pdl;
        cfg.numAttrs = 1;
        cudaLaunchKernelEx(&cfg, outproj_kernel, wo, bo, out);
    }
}

// round 17
// speedup vs baseline: 1.2334x; 1.0201x over previous
#include <cuda_runtime.h>
#include <cstdint>

#define BATCH 32
#define NH    16
#define DK    64
#define DM    1024
#define TC    4096

// Scratch (device globals — no allocation allowed in kernel_launch)
__device__ float g_kp[BATCH * DM];   // new-token key projection
__device__ float g_vp[BATCH * DM];   // new-token value projection
__device__ float g_x [BATCH * DM];   // attention output (pre out-proj)

// Packed dual-FMA (sm_103a FFMA2; PTX-only)
__device__ __forceinline__ void ffma2(unsigned long long& d,
                                      unsigned long long a,
                                      unsigned long long b)
{
    asm("fma.rn.f32x2 %0, %1, %2, %0;" : "+l"(d) : "l"(a), "l"(b));
}
__device__ __forceinline__ float pair_sum(unsigned long long v)
{
    return __uint_as_float((unsigned)v) + __uint_as_float((unsigned)(v >> 32));
}

// ---------------------------------------------------------------------------
// k/v projection ONLY: grid (DM/8, 2, 1) = 256 CTAs, block 128.
// CTA owns 8 rows x ALL 32 batches (8 pipelined cp.async act groups of 4).
// Small grid is deliberate: only ~1.7 kv CTAs/SM, so the PDL-chained
// attention kernel co-schedules ~2.7 CTAs/SM from t=0 and stays at the HBM
// roofline while this kernel's ~24us hides inside attention's ~149us stream
// (R16's 512-CTA grid filled the regfile and blocked co-residency).
// Triggers programmatic completion at entry.
// ---------------------------------------------------------------------------
__global__ void __launch_bounds__(128)
kv_kernel(const float* __restrict__ act,
          const float* __restrict__ Wk, const float* __restrict__ Bk,
          const float* __restrict__ Wv, const float* __restrict__ Bv)
{
    if (threadIdx.x == 0) cudaTriggerProgrammaticLaunchCompletion();

    const float* W    = (blockIdx.y == 0) ? Wk : Wv;
    const float* bias = (blockIdx.y == 0) ? Bk : Bv;
    float* out        = (blockIdx.y == 0) ? g_kp : g_vp;

    const int tid  = threadIdx.x;
    const int warp = tid >> 5;
    const int lane = tid & 31;
    const int j0   = (blockIdx.x * 4 + warp) * 2;

    __shared__ __align__(16) float s_act[2][4 * DM];

#define COMMIT_ACT(g_)                                                       \
    do {                                                                     \
        const float* _src = act + (size_t)((g_) * 4) * DM;                   \
        uint32_t _dst = (uint32_t)__cvta_generic_to_shared(s_act[(g_) & 1]); \
        _Pragma("unroll")                                                    \
        for (int _i = 0; _i < 8; _i++) {                                     \
            int _u = _i * 128 + tid;                                         \
            asm volatile("cp.async.cg.shared.global [%0], [%1], 16;"         \
                         :: "r"(_dst + _u * 16), "l"(_src + _u * 4)          \
                         : "memory");                                        \
        }                                                                    \
        asm volatile("cp.async.commit_group;" ::: "memory");                 \
    } while (0)

    COMMIT_ACT(0);
    COMMIT_ACT(1);

    ulonglong2 w[2][8];
#pragma unroll
    for (int r = 0; r < 2; r++) {
        const float* Wr = W + (size_t)(j0 + r) * DM;
#pragma unroll
        for (int c = 0; c < 8; c++)
            w[r][c] = *(const ulonglong2*)(Wr + c * 128 + lane * 4);
    }
    const float bias0 = bias[j0], bias1 = bias[j0 + 1];

#pragma unroll
    for (int g = 0; g < 8; g++) {
        if (g < 7) asm volatile("cp.async.wait_group 1;" ::: "memory");
        else       asm volatile("cp.async.wait_group 0;" ::: "memory");
        __syncthreads();

        const float* sa = s_act[g & 1];
        unsigned long long a2[4][2];
#pragma unroll
        for (int b = 0; b < 4; b++) { a2[b][0] = 0ull; a2[b][1] = 0ull; }

#pragma unroll
        for (int c = 0; c < 8; c++) {
#pragma unroll
            for (int b = 0; b < 4; b++) {
                ulonglong2 x = *(const ulonglong2*)&sa[b * DM + c * 128 + lane * 4];
                ffma2(a2[b][0], x.x, w[0][c].x);
                ffma2(a2[b][0], x.y, w[0][c].y);
                ffma2(a2[b][1], x.x, w[1][c].x);
                ffma2(a2[b][1], x.y, w[1][c].y);
            }
        }

        float a[4][2];
#pragma unroll
        for (int b = 0; b < 4; b++) {
            a[b][0] = pair_sum(a2[b][0]);
            a[b][1] = pair_sum(a2[b][1]);
        }
#pragma unroll
        for (int off = 16; off; off >>= 1) {
#pragma unroll
            for (int b = 0; b < 4; b++) {
                a[b][0] += __shfl_xor_sync(0xffffffffu, a[b][0], off);
                a[b][1] += __shfl_xor_sync(0xffffffffu, a[b][1], off);
            }
        }

        if (lane == 0) {
            const int bb0 = g * 4;
#pragma unroll
            for (int b = 0; b < 4; b++) {
                out[(size_t)(bb0 + b) * DM + j0]     = a[b][0] + bias0;
                out[(size_t)(bb0 + b) * DM + j0 + 1] = a[b][1] + bias1;
            }
        }

        if (g + 2 < 8) {
            __syncthreads();        // all reads of buf (g&1) done
            COMMIT_ACT(g + 2);
        }
    }
#undef COMMIT_ACT
}

// ---------------------------------------------------------------------------
// Flash-decode attention, self-contained for q (R16-proven):
//  1) prologue: CTA computes its own 64 q-proj outputs (8 rows/warp,
//     wq L2-deduped across the 32 CTAs sharing h).
//  2) stream 4096 cached keys (R7-proven block-softmax body, HBM roofline).
//  3) cudaGridDependencySynchronize() only at the END, before the appended
//     token reads g_kp/g_vp (kv kernel finished ~100us earlier).
// One CTA per (b,h): 512 CTAs x 256 threads, 4 CTAs/SM.
// ---------------------------------------------------------------------------
__global__ void __launch_bounds__(256, 4)
attn_kernel(const float* __restrict__ q,
            const float* __restrict__ wq,
            const float* __restrict__ bq,
            const float* __restrict__ Kc,
            const float* __restrict__ Vc)
{
    const int bh   = blockIdx.x;       // 0..511
    const int b    = bh >> 4;
    const int h    = bh & 15;
    const int warp = threadIdx.x >> 5;
    const int lane = threadIdx.x & 31;
    const int half = lane >> 4;
    const int li   = lane & 15;

    __shared__ __align__(16) float sqf[DK];
    __shared__ float  sm[16], sl[16];
    __shared__ float4 so[16][16];
    __shared__ float  red2[2];

    // ---- q-projection prologue: warp computes rows h*64+warp*8 .. +7 ----
    {
        const float* qb = q + (size_t)b * DM;
        const float* Wq = wq + (size_t)(h * DK + warp * 8) * DM;
        float acc[8];
#pragma unroll
        for (int r = 0; r < 8; r++) acc[r] = 0.0f;
#pragma unroll
        for (int c = 0; c < 8; c++) {
            float4 x = *(const float4*)(qb + c * 128 + lane * 4);
#pragma unroll
            for (int r = 0; r < 8; r++) {
                float4 wv4 = *(const float4*)(Wq + (size_t)r * DM + c * 128 + lane * 4);
                acc[r] += x.x * wv4.x + x.y * wv4.y + x.z * wv4.z + x.w * wv4.w;
            }
        }
#pragma unroll
        for (int off = 16; off; off >>= 1)
#pragma unroll
            for (int r = 0; r < 8; r++)
                acc[r] += __shfl_xor_sync(0xffffffffu, acc[r], off);
        if (lane == 0) {
#pragma unroll
            for (int r = 0; r < 8; r++)
                sqf[warp * 8 + r] = (acc[r] + bq[h * DK + warp * 8 + r]) * 0.125f;
        }
    }
    __syncthreads();

    const float4 q4 = *(const float4*)&sqf[4 * li];

    const float* Kp = Kc + (size_t)bh * TC * DK + (size_t)half * DK + 4 * li;
    const float* Vp = Vc + (size_t)bh * TC * DK + (size_t)half * DK + 4 * li;

    float  m = -1e30f;
    float  l = 0.0f;
    float4 o = make_float4(0.f, 0.f, 0.f, 0.f);

    const int t0 = warp * (TC / 8);
    for (int t = t0; t < t0 + TC / 8; t += 8) {
        float4 kk[4], vv[4];
#pragma unroll
        for (int i = 0; i < 4; i++)
            kk[i] = __ldcs((const float4*)(Kp + (size_t)(t + 2 * i) * DK));
#pragma unroll
        for (int i = 0; i < 4; i++)
            vv[i] = __ldcs((const float4*)(Vp + (size_t)(t + 2 * i) * DK));

        float s[4];
#pragma unroll
        for (int i = 0; i < 4; i++)
            s[i] = kk[i].x * q4.x + kk[i].y * q4.y + kk[i].z * q4.z + kk[i].w * q4.w;
#pragma unroll
        for (int off = 8; off; off >>= 1)
#pragma unroll
            for (int i = 0; i < 4; i++)
                s[i] += __shfl_xor_sync(0xffffffffu, s[i], off);

        float bm = fmaxf(fmaxf(s[0], s[1]), fmaxf(s[2], s[3]));
        float mn = fmaxf(m, bm);

        float p[4];
#pragma unroll
        for (int i = 0; i < 4; i++) p[i] = __expf(s[i] - mn);

        float  lp = 0.0f;
        float4 op = make_float4(0.f, 0.f, 0.f, 0.f);
#pragma unroll
        for (int i = 0; i < 4; i++) {
            lp   += p[i];
            op.x += p[i] * vv[i].x;
            op.y += p[i] * vv[i].y;
            op.z += p[i] * vv[i].z;
            op.w += p[i] * vv[i].w;
        }

        float sc = __expf(m - mn);
        l   = l   * sc + lp;
        o.x = o.x * sc + op.x;
        o.y = o.y * sc + op.y;
        o.z = o.z * sc + op.z;
        o.w = o.w * sc + op.w;
        m   = mn;
    }

    // Publish 16 partial states, then wait for the kv kernel (finished long
    // ago) before touching g_kp/g_vp.
    const int idx = warp * 2 + half;
    if (li == 0) { sm[idx] = m; sl[idx] = l; }
    so[idx][li] = o;
    cudaGridDependencySynchronize();
    __syncthreads();

    // Merge 16 states + appended token.
    float prod = 0.0f, M = -1e30f, L = 0.0f, O = 0.0f, vn = 0.0f;
    if (threadIdx.x < DK) {
        const int d = threadIdx.x;
        M = sm[0];
#pragma unroll
        for (int i = 1; i < 16; i++) M = fmaxf(M, sm[i]);
#pragma unroll
        for (int i = 0; i < 16; i++) {
            float e = __expf(sm[i] - M);
            L += e * sl[i];
            O += e * ((const float*)so[i])[d];
        }
        float kn = g_kp[b * DM + h * DK + d];
        vn       = g_vp[b * DM + h * DK + d];
        prod = sqf[d] * kn;          // q pre-scaled -> new-token score part
    }
#pragma unroll
    for (int off = 16; off; off >>= 1)
        prod += __shfl_xor_sync(0xffffffffu, prod, off);
    if (lane == 0 && warp < 2) red2[warp] = prod;
    __syncthreads();
    if (threadIdx.x < DK) {
        float s_new = red2[0] + red2[1];
        float Mf = fmaxf(M, s_new);
        float ef = __expf(M - Mf);
        float pn = __expf(s_new - Mf);
        float Lf = L * ef + pn;
        float Of = O * ef + pn * vn;
        g_x[b * DM + h * DK + threadIdx.x] = Of / Lf;
    }
}

// ---------------------------------------------------------------------------
// Output projection + PDL (R15-proven): grid (DM/8, 1, 4), block 128.
// Weight preamble overlaps the attention drain; sync, then cp.async act.
// ---------------------------------------------------------------------------
__global__ void __launch_bounds__(128)
outproj_kernel(const float* __restrict__ wo,
               const float* __restrict__ bo,
               float* __restrict__ out)
{
    const int warp = threadIdx.x >> 5;
    const int lane = threadIdx.x & 31;
    const int j0   = (blockIdx.x * 4 + warp) * 2;
    const int b0   = blockIdx.z * 8;

    __shared__ __align__(16) float s_act[2][4 * DM];

    ulonglong2 w[2][8];
#pragma unroll
    for (int r = 0; r < 2; r++) {
        const float* Wr = wo + (size_t)(j0 + r) * DM;
#pragma unroll
        for (int c = 0; c < 8; c++)
            w[r][c] = *(const ulonglong2*)(Wr + c * 128 + lane * 4);
    }
    const float bias0 = bo[j0], bias1 = bo[j0 + 1];

    cudaGridDependencySynchronize();   // g_x complete & visible

    {
        const float* src0 = g_x + (size_t)b0 * DM;
        const float* src1 = g_x + (size_t)(b0 + 4) * DM;
        uint32_t sb0 = (uint32_t)__cvta_generic_to_shared(s_act[0]);
        uint32_t sb1 = (uint32_t)__cvta_generic_to_shared(s_act[1]);
#pragma unroll
        for (int i = 0; i < 8; i++) {
            int u = i * 128 + threadIdx.x;
            asm volatile("cp.async.cg.shared.global [%0], [%1], 16;"
                         :: "r"(sb0 + u * 16), "l"(src0 + u * 4) : "memory");
        }
        asm volatile("cp.async.commit_group;" ::: "memory");
#pragma unroll
        for (int i = 0; i < 8; i++) {
            int u = i * 128 + threadIdx.x;
            asm volatile("cp.async.cg.shared.global [%0], [%1], 16;"
                         :: "r"(sb1 + u * 16), "l"(src1 + u * 4) : "memory");
        }
        asm volatile("cp.async.commit_group;" ::: "memory");
    }

    asm volatile("cp.async.wait_group 1;" ::: "memory");
    __syncthreads();

#pragma unroll
    for (int g = 0; g < 2; g++) {
        const float* sa = s_act[g];
        unsigned long long a2[4][2];
#pragma unroll
        for (int b = 0; b < 4; b++) { a2[b][0] = 0ull; a2[b][1] = 0ull; }

#pragma unroll
        for (int c = 0; c < 8; c++) {
#pragma unroll
            for (int b = 0; b < 4; b++) {
                ulonglong2 x = *(const ulonglong2*)&sa[b * DM + c * 128 + lane * 4];
                ffma2(a2[b][0], x.x, w[0][c].x);
                ffma2(a2[b][0], x.y, w[0][c].y);
                ffma2(a2[b][1], x.x, w[1][c].x);
                ffma2(a2[b][1], x.y, w[1][c].y);
            }
        }

        float a[4][2];
#pragma unroll
        for (int b = 0; b < 4; b++) {
            a[b][0] = pair_sum(a2[b][0]);
            a[b][1] = pair_sum(a2[b][1]);
        }
#pragma unroll
        for (int off = 16; off; off >>= 1) {
#pragma unroll
            for (int b = 0; b < 4; b++) {
                a[b][0] += __shfl_xor_sync(0xffffffffu, a[b][0], off);
                a[b][1] += __shfl_xor_sync(0xffffffffu, a[b][1], off);
            }
        }

        if (lane == 0) {
            const int bb0 = b0 + g * 4;
#pragma unroll
            for (int b = 0; b < 4; b++) {
                out[(size_t)(bb0 + b) * DM + j0]     = a[b][0] + bias0;
                out[(size_t)(bb0 + b) * DM + j0 + 1] = a[b][1] + bias1;
            }
        }
        if (g == 0) {
            asm volatile("cp.async.wait_group 0;" ::: "memory");
            __syncthreads();
        }
    }
}

// ---------------------------------------------------------------------------
// inputs (metadata order): 0 q, 1 key_pre, 2 value_pre,
//   3 wq, 4 bq, 5 wk, 6 bk, 7 wv, 8 bv, 9 wo, 10 bo
// output: [32, 1, 1024] fp32
// ---------------------------------------------------------------------------
extern "C" void kernel_launch(void* const* d_in, const int* in_sizes, int n_in,
                              void* d_out, int out_size)
{
    const float* q   = (const float*)d_in[0];
    const float* Kc  = (const float*)d_in[1];
    const float* Vc  = (const float*)d_in[2];
    const float* wq  = (const float*)d_in[3];
    const float* bq  = (const float*)d_in[4];
    const float* wk  = (const float*)d_in[5];
    const float* bk  = (const float*)d_in[6];
    const float* wv  = (const float*)d_in[7];
    const float* bv  = (const float*)d_in[8];
    const float* wo  = (const float*)d_in[9];
    const float* bo  = (const float*)d_in[10];
    float* out = (float*)d_out;

    // 1) k/v projections: SMALL grid (256 CTAs) so attention co-schedules
    //    immediately after the entry trigger.
    kv_kernel<<<dim3(DM / 8, 2, 1), 128>>>(q, wk, bk, wv, bv);

    cudaLaunchAttribute pdl[1];
    pdl[0].id = cudaLaunchAttributeProgrammaticStreamSerialization;
    pdl[0].val.programmaticStreamSerializationAllowed = 1;

    // 2) Attention (PDL): self-contained q-proj; syncs on kv only at the end.
    {
        cudaLaunchConfig_t cfg = {};
        cfg.gridDim  = dim3(BATCH * NH, 1, 1);
        cfg.blockDim = dim3(256, 1, 1);
        cfg.stream = 0;
        cfg.attrs = pdl;
        cfg.numAttrs = 1;
        cudaLaunchKernelEx(&cfg, attn_kernel, q, wq, bq, Kc, Vc);
    }

    // 3) Output projection (PDL): weight preamble overlaps attention drain.
    {
        cudaLaunchConfig_t cfg = {};
        cfg.gridDim  = dim3(DM / 8, 1, 4);
        cfg.blockDim = dim3(128, 1, 1);
        cfg.stream = 0;
        cfg.attrs = pdl;
        cfg.numAttrs = 1;
        cudaLaunchKernelEx(&cfg, outproj_kernel, wo, bo, out);
    }
}